// round 16
// baseline (speedup 1.0000x reference)
#include <cuda_runtime.h>
#include <cuda_bf16.h>
#include <cuda_fp16.h>
#include <math.h>
#include <stdint.h>

#define MROWS (4 * 8192)          // 32768 rows total
#define DIMK  512
#define NQKV  1536

// ---------------- scratch (device globals; no allocation allowed) ----------
__device__ __half g_qf[MROWS * 512];        // elu(q)+1 fp16
__device__ __half g_kf[MROWS * 512];        // elu(k)+1 fp16
__device__ __half g_vf[MROWS * 512];        // v fp16
__device__ float g_kvpart[32 * 16 * 4160];  // per (bh,chunk): 64x64 kv + 64 ksum
__device__ float g_kv[32 * 4160];
__device__ float g_wt[NQKV * 512];          // w_qkv^T fp32 [n][k]

__device__ __half g_xf[MROWS * 512];        // x single fp16
__device__ __half g_wf[NQKV * 512];         // w^T single fp16
__device__ __half g_qzf[MROWS * 512];       // (q*z*2^15) single fp16
__device__ __half g_wbf[4 * 512 * 512];     // Wbig^T single fp16 [b][j][r]

#define QZ_SCALE 32768.0f
#define QZ_INV   (1.0f / 32768.0f)

// ---------------- helpers ---------------------------------------------------
__device__ __forceinline__ void mma16816h(float* c, const uint32_t* a, const uint32_t* b) {
    asm volatile(
        "mma.sync.aligned.m16n8k16.row.col.f32.f16.f16.f32 "
        "{%0,%1,%2,%3}, {%4,%5,%6,%7}, {%8,%9}, {%0,%1,%2,%3};"
        : "+f"(c[0]), "+f"(c[1]), "+f"(c[2]), "+f"(c[3])
        : "r"(a[0]), "r"(a[1]), "r"(a[2]), "r"(a[3]), "r"(b[0]), "r"(b[1]));
}
__device__ __forceinline__ void ldsm4(uint32_t* r, uint32_t a) {
    asm volatile("ldmatrix.sync.aligned.m8n8.x4.shared.b16 {%0,%1,%2,%3}, [%4];"
        : "=r"(r[0]), "=r"(r[1]), "=r"(r[2]), "=r"(r[3]) : "r"(a));
}
__device__ __forceinline__ uint32_t smem_u32(const void* p) {
    uint32_t a;
    asm("{ .reg .u64 t; cvta.to.shared.u64 t, %1; cvt.u32.u64 %0, t; }" : "=r"(a) : "l"(p));
    return a;
}
__device__ __forceinline__ void cp16(uint32_t s, const void* g) {
    asm volatile("cp.async.cg.shared.global [%0], [%1], 16;" :: "r"(s), "l"(g));
}
__device__ __forceinline__ float elu1(float x) {
    return x >= 0.f ? x + 1.f : __expf(x);
}

// ============================================================================
// W transpose: g_wt[n][k] = W[k][n]   (W: [512][1536])   [R5-verified]
// ============================================================================
__global__ void transpose_w(const float* __restrict__ W)
{
    __shared__ float t[32][33];
    const int bx = blockIdx.x * 32;   // n base
    const int by = blockIdx.y * 32;   // k base
    const int x = threadIdx.x;
    for (int yy = threadIdx.y; yy < 32; yy += 8)
        t[yy][x] = W[(size_t)(by + yy) * NQKV + bx + x];
    __syncthreads();
    for (int yy = threadIdx.y; yy < 32; yy += 8)
        g_wt[(size_t)(bx + yy) * 512 + by + x] = t[x][yy];
}

// ============================================================================
// conv_x_f16: X fp32 -> single fp16 (same index)  [R12-verified]
// ============================================================================
__global__ void conv_x_f16(const float* __restrict__ X)
{
    size_t i4 = (size_t)blockIdx.x * 256 + threadIdx.x;
    float4 v = ((const float4*)X)[i4];
    __half2* O = (__half2*)g_xf;
    O[i4 * 2]     = __floats2half2_rn(v.x, v.y);
    O[i4 * 2 + 1] = __floats2half2_rn(v.z, v.w);
}

// ============================================================================
// conv_w_f16: g_wt fp32 -> single fp16 (same index)  [R14-verified]
// ============================================================================
__global__ void conv_w_f16()
{
    size_t i = (size_t)blockIdx.x * 256 + threadIdx.x;
    g_wf[i] = __float2half_rn(g_wt[i]);
}

// ============================================================================
// z_split: fused compute_z + qz conversion; q read as fp16.  [R15-verified]
// ============================================================================
__global__ __launch_bounds__(128) void z_split()
{
    const int row = blockIdx.x;            // 0..32767
    const int b = row >> 13;
    const int t = threadIdx.x;             // 0..127
    const int h = t >> 4;
    const int e = t * 4;
    const int d = e & 63;

    size_t o2 = ((size_t)row * 512 + e) >> 1;
    __half2 q01 = ((const __half2*)g_qf)[o2];
    __half2 q23 = ((const __half2*)g_qf)[o2 + 1];
    float qx = __half2float(__low2half(q01)),  qy = __half2float(__high2half(q01));
    float qz2 = __half2float(__low2half(q23)), qw = __half2float(__high2half(q23));

    const float* ks = g_kv + (size_t)(b * 8 + h) * 4160 + 4096 + d;
    float part = qx * ks[0] + qy * ks[1] + qz2 * ks[2] + qw * ks[3];
#pragma unroll
    for (int off = 8; off; off >>= 1)
        part += __shfl_xor_sync(0xFFFFFFFFu, part, off);
    const float zs = QZ_SCALE / (part + 1e-6f);

    __half2* O = (__half2*)g_qzf;
    O[o2]     = __floats2half2_rn(qx * zs, qy * zs);
    O[o2 + 1] = __floats2half2_rn(qz2 * zs, qw * zs);
}

// ============================================================================
// fp16 single-product GEMM, K-chunks of 32: C = A @ B.
// C tile 128x128, K=512 in 16 chunks of 32. Rows 64B, 4 slots of 16B;
// swizzle slot = k8 ^ ((row>>1)&3) (conflict-free; invariant under
// mt*16/ntp*16/wm/wn row offsets). Chunk buffer = 2 arrays x 8KB = 16KB;
// 3 buffers = 48KB static smem; depth-2 cp.async pipeline.
// MODE 0: A=x, B=Wqkv^T -> q/k/v fp16 with elu+1 on q,k
// MODE 1: A=qz*2^15, B=Wbig^T[b] -> Out = C*2^-15 + bias (fp32)
// ============================================================================
#define ABYTES 8192                    // one array: 128 rows x 64 B
#define BUF0B (2 * ABYTES)             // 16384 B per chunk buffer

template <int MODE>
__global__ __launch_bounds__(256, 2) void gemm_f16(
    const __half* __restrict__ Ag, const __half* __restrict__ Bg,
    const float* __restrict__ bias, float* __restrict__ Out)
{
    __shared__ __half smem[3 * BUF0B / 2];   // 48 KB

    const int tid = threadIdx.x;
    const int wid = tid >> 5, lane = tid & 31;
    const int g = lane >> 2, tig = lane & 3;
    const int m0 = blockIdx.y * 128;
    const int n0 = blockIdx.x * 128;
    const int wm = (wid & 1) * 64;
    const int wn = (wid >> 1) * 32;
    const int bb = m0 >> 13;          // batch (tiles never straddle batches)

    const __half* B = Bg + (MODE == 1 ? (size_t)bb * 262144 : 0);

    // fill mapping: thread t -> row = t>>1; k8 slots j0 = t&1 and j0+2
    const int frow = tid >> 1, fj0 = tid & 1;
    const int fsw = (frow >> 1) & 3;
    const uint32_t sOffA0 = (uint32_t)(frow * 64 + ((fj0 ^ fsw) * 16));
    const uint32_t sOffA1 = (uint32_t)(frow * 64 + (((fj0 + 2) ^ fsw) * 16));
    const __half* gaBase = Ag + (size_t)(m0 + frow) * 512;
    const __half* gbBase = B  + (size_t)(n0 + frow) * 512;

    const uint32_t sBase = smem_u32(smem);

    // ldmatrix per-lane offsets, one per k16 half (ks), swizzled
    const int ar = lane & 15, akh = lane >> 4;          // A row-in-16, k8 bit
    const int asw = (ar >> 1) & 3;
    const uint32_t aoff0 =
        (uint32_t)((wm + ar) * 64 + (((0 * 2 + akh) ^ asw) * 16));
    const uint32_t aoff1 =
        (uint32_t)((wm + ar) * 64 + (((1 * 2 + akh) ^ asw) * 16));
    const int brl = ((lane >> 4) & 1) * 8 + (lane & 7); // B row-in-16
    const int bkh = (lane >> 3) & 1;
    const int bsw = (brl >> 1) & 3;
    const uint32_t boff0 =
        (uint32_t)((wn + brl) * 64 + (((0 * 2 + bkh) ^ bsw) * 16));
    const uint32_t boff1 =
        (uint32_t)((wn + brl) * 64 + (((1 * 2 + bkh) ^ bsw) * 16));

    auto issue = [&](int k0, int bufI) {
        const uint32_t nb = sBase + (uint32_t)(bufI * BUF0B);
        cp16(nb + 0 * ABYTES + sOffA0, gaBase + k0 + fj0 * 8);
        cp16(nb + 0 * ABYTES + sOffA1, gaBase + k0 + (fj0 + 2) * 8);
        cp16(nb + 1 * ABYTES + sOffA0, gbBase + k0 + fj0 * 8);
        cp16(nb + 1 * ABYTES + sOffA1, gbBase + k0 + (fj0 + 2) * 8);
        asm volatile("cp.async.commit_group;" ::: "memory");
    };

    float acc[4][4][4];
#pragma unroll
    for (int i = 0; i < 4; i++)
#pragma unroll
        for (int j = 0; j < 4; j++)
#pragma unroll
            for (int t = 0; t < 4; t++) acc[i][j][t] = 0.f;

    // ---- prologue: chunks 0,1 into buffers 0,1 ----
    issue(0, 0);
    issue(32, 1);

    for (int kc = 0; kc < 16; kc++) {
        if (kc < 15) {
            asm volatile("cp.async.wait_group 1;" ::: "memory");  // chunk kc landed
        } else {
            asm volatile("cp.async.wait_group 0;" ::: "memory");
        }
        __syncthreads();   // data visible; all warps done with buf (kc+2)%3

        if (kc < 14) issue((kc + 2) * 32, (kc + 2) % 3);

        const uint32_t cb = sBase + (uint32_t)((kc % 3) * BUF0B);
        const uint32_t aB = cb;
        const uint32_t bB = cb + ABYTES;

#pragma unroll
        for (int ks = 0; ks < 2; ks++) {
            const uint32_t ao = (ks == 0) ? aoff0 : aoff1;
            const uint32_t bo = (ks == 0) ? boff0 : boff1;
            uint32_t a4[4][4];
#pragma unroll
            for (int mt = 0; mt < 4; mt++)
                ldsm4(a4[mt], aB + ao + (uint32_t)(mt * 1024));
#pragma unroll
            for (int ntp = 0; ntp < 2; ntp++) {
                uint32_t b4[4];
                ldsm4(b4, bB + bo + (uint32_t)(ntp * 1024));
#pragma unroll
                for (int half = 0; half < 2; half++) {
                    const int nt = ntp * 2 + half;
                    const uint32_t* bfrag = b4 + half * 2;
#pragma unroll
                    for (int mt = 0; mt < 4; mt++)
                        mma16816h(acc[mt][nt], a4[mt], bfrag);
                }
            }
        }
    }

    // -------- epilogue [R14/R15-verified] --------
    if (MODE == 0) {
        __half* dst = (n0 < 512) ? g_qf : (n0 < 1024 ? g_kf : g_vf);
        const bool act = (n0 < 1024);
        const int cb2 = (n0 & 511) + wn;
#pragma unroll
        for (int mt = 0; mt < 4; mt++) {
            int r0 = m0 + wm + mt * 16 + g;
#pragma unroll
            for (int nt = 0; nt < 4; nt++) {
                int c = cb2 + nt * 8 + tig * 2;
                float v0 = acc[mt][nt][0], v1 = acc[mt][nt][1];
                float v2 = acc[mt][nt][2], v3 = acc[mt][nt][3];
                if (act) { v0 = elu1(v0); v1 = elu1(v1); v2 = elu1(v2); v3 = elu1(v3); }
                *(__half2*)&dst[(size_t)r0 * 512 + c]       = __floats2half2_rn(v0, v1);
                *(__half2*)&dst[(size_t)(r0 + 8) * 512 + c] = __floats2half2_rn(v2, v3);
            }
        }
    } else {
        const int cb2 = n0 + wn;
#pragma unroll
        for (int mt = 0; mt < 4; mt++) {
            int r0 = m0 + wm + mt * 16 + g;
#pragma unroll
            for (int nt = 0; nt < 4; nt++) {
                int c = cb2 + nt * 8 + tig * 2;
                float b0 = bias[c], b1 = bias[c + 1];
                *(float2*)&Out[(size_t)r0 * 512 + c] =
                    make_float2(acc[mt][nt][0] * QZ_INV + b0,
                                acc[mt][nt][1] * QZ_INV + b1);
                *(float2*)&Out[(size_t)(r0 + 8) * 512 + c] =
                    make_float2(acc[mt][nt][2] * QZ_INV + b0,
                                acc[mt][nt][3] * QZ_INV + b1);
            }
        }
    }
}

// ============================================================================
// kv partial reduce (fp32 accum from fp16 inputs) [R15-verified]
// ============================================================================
__global__ __launch_bounds__(256, 4) void kv_reduce()
{
    __shared__ float ks[8][64];
    __shared__ float vs[8][64];
    const int bh = blockIdx.x;
    const int b = bh >> 3, h = bh & 7;
    const int nbase = blockIdx.y * 512;
    const int tid = threadIdx.x;
    const int tx = tid & 15, ty = tid >> 4;

    float acc[4][4];
#pragma unroll
    for (int i = 0; i < 4; i++)
#pragma unroll
        for (int j = 0; j < 4; j++) acc[i][j] = 0.f;
    float ksacc[4] = {0.f, 0.f, 0.f, 0.f};

    const int lr = (tid & 127) >> 4;
    const int lc = tid & 15;
    const __half* src = (tid < 128) ? g_kf : g_vf;
    float* sdst = (tid < 128) ? &ks[lr][lc * 4] : &vs[lr][lc * 4];

    for (int r0 = 0; r0 < 512; r0 += 8) {
        int n = nbase + r0 + lr;
        uint2 raw = *(const uint2*)&src[((size_t)(b * 8192 + n)) * 512 + h * 64 + lc * 4];
        __half2 p0 = *(__half2*)&raw.x;
        __half2 p1 = *(__half2*)&raw.y;
        float4 val;
        val.x = __half2float(__low2half(p0));
        val.y = __half2float(__high2half(p0));
        val.z = __half2float(__low2half(p1));
        val.w = __half2float(__high2half(p1));
        *(float4*)sdst = val;
        __syncthreads();
#pragma unroll
        for (int r = 0; r < 8; r++) {
            float kf[4], vf[4];
            *(float4*)kf = *(float4*)&ks[r][tx * 4];
            *(float4*)vf = *(float4*)&vs[r][ty * 4];
#pragma unroll
            for (int i = 0; i < 4; i++)
#pragma unroll
                for (int j = 0; j < 4; j++) acc[i][j] += kf[i] * vf[j];
            if (ty == 0) {
#pragma unroll
                for (int i = 0; i < 4; i++) ksacc[i] += kf[i];
            }
        }
        __syncthreads();
    }

    const size_t base = (size_t)(bh * 16 + blockIdx.y) * 4160;
#pragma unroll
    for (int i = 0; i < 4; i++)
#pragma unroll
        for (int j = 0; j < 4; j++)
            g_kvpart[base + (tx * 4 + i) * 64 + ty * 4 + j] = acc[i][j];
    if (ty == 0) {
#pragma unroll
        for (int i = 0; i < 4; i++) g_kvpart[base + 4096 + tx * 4 + i] = ksacc[i];
    }
}

__global__ void kv_combine()
{
    const int bh = blockIdx.x;
    const int i0 = blockIdx.y * 260;
    const int iend = (i0 + 260 < 4160) ? i0 + 260 : 4160;
    for (int i = i0 + threadIdx.x; i < iend; i += 256) {
        float s = 0.f;
#pragma unroll
        for (int c = 0; c < 16; c++) s += g_kvpart[(size_t)(bh * 16 + c) * 4160 + i];
        g_kv[(size_t)bh * 4160 + i] = s;
    }
}

// ============================================================================
// Wbig^T single fp16 [R14-verified]
// ============================================================================
__global__ void make_wbig(const float* __restrict__ Wout)
{
    const int r = blockIdx.x;          // h*64+d
    const int b = blockIdx.y;
    const int h = r >> 6, d = r & 63;
    __shared__ float kvrow[64];
    if (threadIdx.x < 64)
        kvrow[threadIdx.x] = g_kv[(size_t)(b * 8 + h) * 4160 + d * 64 + threadIdx.x];
    __syncthreads();
    float acc[4] = {0.f, 0.f, 0.f, 0.f};
    for (int m = 0; m < 64; m++) {
        float kvv = kvrow[m];
        const float* wrow = Wout + (size_t)(h * 64 + m) * 512;
#pragma unroll
        for (int i = 0; i < 4; i++) acc[i] += kvv * wrow[threadIdx.x + i * 128];
    }
#pragma unroll
    for (int i = 0; i < 4; i++) {
        int j = threadIdx.x + i * 128;
        g_wbf[(size_t)b * 262144 + (size_t)j * 512 + r] = __float2half_rn(acc[i]);
    }
}

// ============================================================================
extern "C" void kernel_launch(void* const* d_in, const int* in_sizes, int n_in,
                              void* d_out, int out_size)
{
    const float* x     = (const float*)d_in[0];   // [4,8192,512]
    const float* w_qkv = (const float*)d_in[1];   // [512,1536]
    const float* w_out = (const float*)d_in[2];   // [512,512]
    const float* b_out = (const float*)d_in[3];   // [512]
    float* out = (float*)d_out;                   // [4,8192,512]

    __half *xf_p, *wf_p, *qzf_p, *wbf_p;
    cudaGetSymbolAddress((void**)&xf_p,  g_xf);
    cudaGetSymbolAddress((void**)&wf_p,  g_wf);
    cudaGetSymbolAddress((void**)&qzf_p, g_qzf);
    cudaGetSymbolAddress((void**)&wbf_p, g_wbf);

    transpose_w<<<dim3(48, 16), dim3(32, 8)>>>(w_qkv);
    conv_x_f16<<<16384, 256>>>(x);
    conv_w_f16<<<3072, 256>>>();
    gemm_f16<0><<<dim3(12, 256), 256>>>(xf_p, wf_p, nullptr, nullptr);
    kv_reduce<<<dim3(32, 16), 256>>>();
    kv_combine<<<dim3(32, 16), 256>>>();
    make_wbig<<<dim3(512, 4), 128>>>(w_out);
    z_split<<<32768, 128>>>();
    gemm_f16<1><<<dim3(4, 256), 256>>>(qzf_p, wbf_p, b_out, out);
}

// round 17
// speedup vs baseline: 1.2137x; 1.2137x over previous
#include <cuda_runtime.h>
#include <cuda_bf16.h>
#include <cuda_fp16.h>
#include <math.h>
#include <stdint.h>

#define MROWS (4 * 8192)          // 32768 rows total
#define DIMK  512
#define NQKV  1536

// ---------------- scratch (device globals; no allocation allowed) ----------
__device__ __half g_qf[MROWS * 512];        // elu(q)+1 fp16
__device__ __half g_kf[MROWS * 512];        // elu(k)+1 fp16
__device__ __half g_vf[MROWS * 512];        // v fp16
__device__ float g_kvpart[32 * 16 * 4160];  // per (bh,chunk): 64x64 kv + 64 ksum
__device__ float g_kv[32 * 4160];
__device__ float g_wt[NQKV * 512];          // w_qkv^T fp32 [n][k]

__device__ __half g_xf[MROWS * 512];        // x single fp16
__device__ __half g_wf[NQKV * 512];         // w^T single fp16
__device__ __half g_qzf[MROWS * 512];       // (q*z*2^15) single fp16
__device__ __half g_wbf[4 * 512 * 512];     // Wbig^T single fp16 [b][j][r]

#define QZ_SCALE 32768.0f
#define QZ_INV   (1.0f / 32768.0f)

// ---------------- helpers ---------------------------------------------------
__device__ __forceinline__ void mma16816h(float* c, const uint32_t* a, const uint32_t* b) {
    asm volatile(
        "mma.sync.aligned.m16n8k16.row.col.f32.f16.f16.f32 "
        "{%0,%1,%2,%3}, {%4,%5,%6,%7}, {%8,%9}, {%0,%1,%2,%3};"
        : "+f"(c[0]), "+f"(c[1]), "+f"(c[2]), "+f"(c[3])
        : "r"(a[0]), "r"(a[1]), "r"(a[2]), "r"(a[3]), "r"(b[0]), "r"(b[1]));
}
__device__ __forceinline__ void ldsm4(uint32_t* r, uint32_t a) {
    asm volatile("ldmatrix.sync.aligned.m8n8.x4.shared.b16 {%0,%1,%2,%3}, [%4];"
        : "=r"(r[0]), "=r"(r[1]), "=r"(r[2]), "=r"(r[3]) : "r"(a));
}
__device__ __forceinline__ void ldsm4t(uint32_t* r, uint32_t a) {
    asm volatile("ldmatrix.sync.aligned.m8n8.x4.trans.shared.b16 {%0,%1,%2,%3}, [%4];"
        : "=r"(r[0]), "=r"(r[1]), "=r"(r[2]), "=r"(r[3]) : "r"(a));
}
__device__ __forceinline__ uint32_t smem_u32(const void* p) {
    uint32_t a;
    asm("{ .reg .u64 t; cvta.to.shared.u64 t, %1; cvt.u32.u64 %0, t; }" : "=r"(a) : "l"(p));
    return a;
}
__device__ __forceinline__ void cp16(uint32_t s, const void* g) {
    asm volatile("cp.async.cg.shared.global [%0], [%1], 16;" :: "r"(s), "l"(g));
}
__device__ __forceinline__ float elu1(float x) {
    return x >= 0.f ? x + 1.f : __expf(x);
}

// ============================================================================
// W transpose: g_wt[n][k] = W[k][n]   (W: [512][1536])   [R5-verified]
// ============================================================================
__global__ void transpose_w(const float* __restrict__ W)
{
    __shared__ float t[32][33];
    const int bx = blockIdx.x * 32;   // n base
    const int by = blockIdx.y * 32;   // k base
    const int x = threadIdx.x;
    for (int yy = threadIdx.y; yy < 32; yy += 8)
        t[yy][x] = W[(size_t)(by + yy) * NQKV + bx + x];
    __syncthreads();
    for (int yy = threadIdx.y; yy < 32; yy += 8)
        g_wt[(size_t)(bx + yy) * 512 + by + x] = t[x][yy];
}

// ============================================================================
// conv_x_f16: X fp32 -> single fp16 (same index)  [R12-verified]
// ============================================================================
__global__ void conv_x_f16(const float* __restrict__ X)
{
    size_t i4 = (size_t)blockIdx.x * 256 + threadIdx.x;
    float4 v = ((const float4*)X)[i4];
    __half2* O = (__half2*)g_xf;
    O[i4 * 2]     = __floats2half2_rn(v.x, v.y);
    O[i4 * 2 + 1] = __floats2half2_rn(v.z, v.w);
}

// ============================================================================
// conv_w_f16: g_wt fp32 -> single fp16 (same index)  [R14-verified]
// ============================================================================
__global__ void conv_w_f16()
{
    size_t i = (size_t)blockIdx.x * 256 + threadIdx.x;
    g_wf[i] = __float2half_rn(g_wt[i]);
}

// ============================================================================
// z_split: fused compute_z + qz conversion; q read as fp16.  [R15-verified]
// ============================================================================
__global__ __launch_bounds__(128) void z_split()
{
    const int row = blockIdx.x;            // 0..32767
    const int b = row >> 13;
    const int t = threadIdx.x;             // 0..127
    const int h = t >> 4;
    const int e = t * 4;
    const int d = e & 63;

    size_t o2 = ((size_t)row * 512 + e) >> 1;
    __half2 q01 = ((const __half2*)g_qf)[o2];
    __half2 q23 = ((const __half2*)g_qf)[o2 + 1];
    float qx = __half2float(__low2half(q01)),  qy = __half2float(__high2half(q01));
    float qz2 = __half2float(__low2half(q23)), qw = __half2float(__high2half(q23));

    const float* ks = g_kv + (size_t)(b * 8 + h) * 4160 + 4096 + d;
    float part = qx * ks[0] + qy * ks[1] + qz2 * ks[2] + qw * ks[3];
#pragma unroll
    for (int off = 8; off; off >>= 1)
        part += __shfl_xor_sync(0xFFFFFFFFu, part, off);
    const float zs = QZ_SCALE / (part + 1e-6f);

    __half2* O = (__half2*)g_qzf;
    O[o2]     = __floats2half2_rn(qx * zs, qy * zs);
    O[o2 + 1] = __floats2half2_rn(qz2 * zs, qw * zs);
}

// ============================================================================
// fp16 single-product GEMM [R14/R15-verified]: C = A @ B.
// C tile 128x128, K=512 in 32 chunks of 16. XOR-swizzled 32B rows;
// chunk buffer = 2 arrays x 4096B = 8KB; 4 buffers = 32KB static smem;
// 4-stage cp.async pipeline.
// MODE 0: A=x, B=Wqkv^T -> q/k/v fp16 with elu+1 on q,k
// MODE 1: A=qz*2^15, B=Wbig^T[b] -> Out = C*2^-15 + bias (fp32)
// ============================================================================
#define ABYTES 4096                    // one array: 128 rows x 32 B
#define BUF0B (2 * ABYTES)             // 8192 B per chunk buffer

template <int MODE>
__global__ __launch_bounds__(256, 2) void gemm_f16(
    const __half* __restrict__ Ag, const __half* __restrict__ Bg,
    const float* __restrict__ bias, float* __restrict__ Out)
{
    __shared__ __half smem[4 * BUF0B / 2];   // 32 KB

    const int tid = threadIdx.x;
    const int wid = tid >> 5, lane = tid & 31;
    const int g = lane >> 2, tig = lane & 3;
    const int m0 = blockIdx.y * 128;
    const int n0 = blockIdx.x * 128;
    const int wm = (wid & 1) * 64;
    const int wn = (wid >> 1) * 32;
    const int bb = m0 >> 13;          // batch (tiles never straddle batches)

    const __half* B = Bg + (MODE == 1 ? (size_t)bb * 262144 : 0);

    const int frow = tid >> 1, fj = tid & 1;
    const int fslot = fj ^ ((frow >> 2) & 1);
    const uint32_t sOff = (uint32_t)(frow * 32 + fslot * 16);
    const __half* ga = Ag + (size_t)(m0 + frow) * 512 + fj * 8;
    const __half* gb = B  + (size_t)(n0 + frow) * 512 + fj * 8;

    const uint32_t sBase = smem_u32(smem);

    const int ar = lane & 15, akh = lane >> 4;
    const uint32_t aoff =
        (uint32_t)((wm + ar) * 32 + ((akh ^ ((ar >> 2) & 1)) * 16));
    const int brl = ((lane >> 4) & 1) * 8 + (lane & 7);
    const int bkh = (lane >> 3) & 1;
    const uint32_t boff =
        (uint32_t)((wn + brl) * 32 + ((bkh ^ (((lane & 7) >> 2) & 1)) * 16));

    auto issue = [&](int k0, int bufI) {
        const uint32_t nb = sBase + (uint32_t)(bufI * BUF0B);
        cp16(nb + 0 * ABYTES + sOff, ga + k0);
        cp16(nb + 1 * ABYTES + sOff, gb + k0);
        asm volatile("cp.async.commit_group;" ::: "memory");
    };

    float acc[4][4][4];
#pragma unroll
    for (int i = 0; i < 4; i++)
#pragma unroll
        for (int j = 0; j < 4; j++)
#pragma unroll
            for (int t = 0; t < 4; t++) acc[i][j][t] = 0.f;

    issue(0, 0);
    issue(16, 1);
    issue(32, 2);

    for (int kc = 0; kc < 32; kc++) {
        if (kc < 30) {
            asm volatile("cp.async.wait_group 2;" ::: "memory");
        } else if (kc == 30) {
            asm volatile("cp.async.wait_group 1;" ::: "memory");
        } else {
            asm volatile("cp.async.wait_group 0;" ::: "memory");
        }
        __syncthreads();

        if (kc <= 28) issue((kc + 3) * 16, (kc + 3) & 3);

        const uint32_t cb = sBase + (uint32_t)((kc & 3) * BUF0B);
        const uint32_t aBase = cb + aoff;
        const uint32_t bBase = cb + ABYTES + boff;

        uint32_t a4[4][4];
#pragma unroll
        for (int mt = 0; mt < 4; mt++)
            ldsm4(a4[mt], aBase + (uint32_t)(mt * 512));
#pragma unroll
        for (int ntp = 0; ntp < 2; ntp++) {
            uint32_t b4[4];
            ldsm4(b4, bBase + (uint32_t)(ntp * 512));
#pragma unroll
            for (int half = 0; half < 2; half++) {
                const int nt = ntp * 2 + half;
                const uint32_t* bfrag = b4 + half * 2;
#pragma unroll
                for (int mt = 0; mt < 4; mt++)
                    mma16816h(acc[mt][nt], a4[mt], bfrag);
            }
        }
    }

    if (MODE == 0) {
        __half* dst = (n0 < 512) ? g_qf : (n0 < 1024 ? g_kf : g_vf);
        const bool act = (n0 < 1024);
        const int cb2 = (n0 & 511) + wn;
#pragma unroll
        for (int mt = 0; mt < 4; mt++) {
            int r0 = m0 + wm + mt * 16 + g;
#pragma unroll
            for (int nt = 0; nt < 4; nt++) {
                int c = cb2 + nt * 8 + tig * 2;
                float v0 = acc[mt][nt][0], v1 = acc[mt][nt][1];
                float v2 = acc[mt][nt][2], v3 = acc[mt][nt][3];
                if (act) { v0 = elu1(v0); v1 = elu1(v1); v2 = elu1(v2); v3 = elu1(v3); }
                *(__half2*)&dst[(size_t)r0 * 512 + c]       = __floats2half2_rn(v0, v1);
                *(__half2*)&dst[(size_t)(r0 + 8) * 512 + c] = __floats2half2_rn(v2, v3);
            }
        }
    } else {
        const int cb2 = n0 + wn;
#pragma unroll
        for (int mt = 0; mt < 4; mt++) {
            int r0 = m0 + wm + mt * 16 + g;
#pragma unroll
            for (int nt = 0; nt < 4; nt++) {
                int c = cb2 + nt * 8 + tig * 2;
                float b0 = bias[c], b1 = bias[c + 1];
                *(float2*)&Out[(size_t)r0 * 512 + c] =
                    make_float2(acc[mt][nt][0] * QZ_INV + b0,
                                acc[mt][nt][1] * QZ_INV + b1);
                *(float2*)&Out[(size_t)(r0 + 8) * 512 + c] =
                    make_float2(acc[mt][nt][2] * QZ_INV + b0,
                                acc[mt][nt][3] * QZ_INV + b1);
            }
        }
    }
}

// ============================================================================
// kv_reduce_mma: per (bh, chunk of 512 n): partial kv[64][64] = k^T @ v and
// ksum[64], via tensor cores + ldmatrix.trans.
// smem: k and v tiles [128 n][64 feat] (128B rows, 8 slots, slot^(n&7) swizz).
// A = k^T (d x n) via ldsm4.trans; B = v col-major (n x m) via ldsm4.trans.
// 8 warps: 2(d) x 4(m), warp tile 32d x 16m. fp32 MMA accumulation.
// ============================================================================
__global__ __launch_bounds__(256) void kv_reduce_mma()
{
    __shared__ __half sk[128 * 64];     // 16 KB
    __shared__ __half sv[128 * 64];     // 16 KB
    __shared__ float skred[8][64];

    const int bh = blockIdx.x;
    const int b = bh >> 3, h = bh & 7;
    const int nbase0 = blockIdx.y * 512;
    const int tid = threadIdx.x;
    const int wid = tid >> 5, lane = tid & 31;
    const int g = lane >> 2, tig = lane & 3;
    const int wmD = (wid & 1) * 32;    // d base of warp tile
    const int wnM = (wid >> 1) * 16;   // m base of warp tile

    const uint32_t skB = smem_u32(sk);
    const uint32_t svB = smem_u32(sv);

    // fill: thread t -> row = t>>1, slots j = (t&1)*4 .. +3 (64B)
    const int frow = tid >> 1;
    const int fj0 = (tid & 1) * 4;
    const __half* gk = g_kf + ((size_t)(b * 8192 + nbase0 + frow)) * 512 + h * 64;
    const __half* gv = g_vf + ((size_t)(b * 8192 + nbase0 + frow)) * 512 + h * 64;

    // ldsm.trans lane patterns (derived from PTX fragment tables):
    // A (k^T): matrices {dlo/nlo, dhi/nlo, dlo/nhi, dhi/nhi}
    const int anr = ((lane >> 4) & 1) * 8 + (lane & 7);   // n row within 16
    const int adb = (lane >> 3) & 1;                      // +8 d
    // B (v col-major): matrices {nlo/mlo, nhi/mlo, nlo/mhi, nhi/mhi}
    const int bnr = ((lane >> 3) & 1) * 8 + (lane & 7);
    const int bmb = (lane >> 4) & 1;                      // +8 m

    float acc[2][2][4];
#pragma unroll
    for (int i = 0; i < 2; i++)
#pragma unroll
        for (int j = 0; j < 2; j++)
#pragma unroll
            for (int t = 0; t < 4; t++) acc[i][j][t] = 0.f;

    // ksum: thread handles d pair (ksd2, ksd2+1), n-range group ksq8
    const int ksd2 = (tid & 31) * 2, ksq8 = tid >> 5;
    float kss0 = 0.f, kss1 = 0.f;

    for (int sc = 0; sc < 4; sc++) {
        __syncthreads();   // previous compute done before overwrite
#pragma unroll
        for (int j = 0; j < 4; j++) {
            int slot = fj0 + j;
            uint32_t so = (uint32_t)(frow * 128 + ((slot ^ (frow & 7)) * 16));
            cp16(skB + so, gk + (size_t)sc * 65536 + slot * 8);
            cp16(svB + so, gv + (size_t)sc * 65536 + slot * 8);
        }
        asm volatile("cp.async.commit_group;" ::: "memory");
        asm volatile("cp.async.wait_group 0;" ::: "memory");
        __syncthreads();

        // ---- MMA: 8 n16 steps ----
#pragma unroll
        for (int ks = 0; ks < 8; ks++) {
            const int an = ks * 16 + anr;
            const int bn = ks * 16 + bnr;
            uint32_t a4[2][4];
#pragma unroll
            for (int mt = 0; mt < 2; mt++) {
                int dslot = ((wmD + mt * 16) >> 3) + adb;
                ldsm4t(a4[mt], skB + (uint32_t)(an * 128 + ((dslot ^ (an & 7)) * 16)));
            }
            uint32_t b4[4];
            {
                int mslot = (wnM >> 3) + bmb;
                ldsm4t(b4, svB + (uint32_t)(bn * 128 + ((mslot ^ (bn & 7)) * 16)));
            }
#pragma unroll
            for (int nt = 0; nt < 2; nt++)
#pragma unroll
                for (int mt = 0; mt < 2; mt++)
                    mma16816h(acc[mt][nt], a4[mt], b4 + nt * 2);
        }

        // ---- ksum from staged k tile (half2 reads) ----
        const int dslot = ksd2 >> 3, dlo = ksd2 & 7;
#pragma unroll
        for (int nn = 0; nn < 16; nn++) {
            int n = ksq8 * 16 + nn;
            __half2 p = *(const __half2*)&sk[n * 64 + ((dslot ^ (n & 7)) * 8) + dlo];
            kss0 += __half2float(__low2half(p));
            kss1 += __half2float(__high2half(p));
        }
    }

    // ---- epilogue: partial kv + ksum ----
    __syncthreads();
    skred[ksq8][ksd2]     = kss0;
    skred[ksq8][ksd2 + 1] = kss1;

    const size_t base = (size_t)(bh * 16 + blockIdx.y) * 4160;
#pragma unroll
    for (int mt = 0; mt < 2; mt++) {
#pragma unroll
        for (int nt = 0; nt < 2; nt++) {
            int d0 = wmD + mt * 16 + g;
            int m = wnM + nt * 8 + tig * 2;
            *(float2*)&g_kvpart[base + (size_t)d0 * 64 + m] =
                make_float2(acc[mt][nt][0], acc[mt][nt][1]);
            *(float2*)&g_kvpart[base + (size_t)(d0 + 8) * 64 + m] =
                make_float2(acc[mt][nt][2], acc[mt][nt][3]);
        }
    }
    __syncthreads();
    if (tid < 64) {
        float s = 0.f;
#pragma unroll
        for (int qq = 0; qq < 8; qq++) s += skred[qq][tid];
        g_kvpart[base + 4096 + tid] = s;
    }
}

__global__ void kv_combine()
{
    const int bh = blockIdx.x;
    const int i0 = blockIdx.y * 260;
    const int iend = (i0 + 260 < 4160) ? i0 + 260 : 4160;
    for (int i = i0 + threadIdx.x; i < iend; i += 256) {
        float s = 0.f;
#pragma unroll
        for (int c = 0; c < 16; c++) s += g_kvpart[(size_t)(bh * 16 + c) * 4160 + i];
        g_kv[(size_t)bh * 4160 + i] = s;
    }
}

// ============================================================================
// Wbig^T single fp16 [R14-verified]
// ============================================================================
__global__ void make_wbig(const float* __restrict__ Wout)
{
    const int r = blockIdx.x;          // h*64+d
    const int b = blockIdx.y;
    const int h = r >> 6, d = r & 63;
    __shared__ float kvrow[64];
    if (threadIdx.x < 64)
        kvrow[threadIdx.x] = g_kv[(size_t)(b * 8 + h) * 4160 + d * 64 + threadIdx.x];
    __syncthreads();
    float acc[4] = {0.f, 0.f, 0.f, 0.f};
    for (int m = 0; m < 64; m++) {
        float kvv = kvrow[m];
        const float* wrow = Wout + (size_t)(h * 64 + m) * 512;
#pragma unroll
        for (int i = 0; i < 4; i++) acc[i] += kvv * wrow[threadIdx.x + i * 128];
    }
#pragma unroll
    for (int i = 0; i < 4; i++) {
        int j = threadIdx.x + i * 128;
        g_wbf[(size_t)b * 262144 + (size_t)j * 512 + r] = __float2half_rn(acc[i]);
    }
}

// ============================================================================
extern "C" void kernel_launch(void* const* d_in, const int* in_sizes, int n_in,
                              void* d_out, int out_size)
{
    const float* x     = (const float*)d_in[0];   // [4,8192,512]
    const float* w_qkv = (const float*)d_in[1];   // [512,1536]
    const float* w_out = (const float*)d_in[2];   // [512,512]
    const float* b_out = (const float*)d_in[3];   // [512]
    float* out = (float*)d_out;                   // [4,8192,512]

    __half *xf_p, *wf_p, *qzf_p, *wbf_p;
    cudaGetSymbolAddress((void**)&xf_p,  g_xf);
    cudaGetSymbolAddress((void**)&wf_p,  g_wf);
    cudaGetSymbolAddress((void**)&qzf_p, g_qzf);
    cudaGetSymbolAddress((void**)&wbf_p, g_wbf);

    transpose_w<<<dim3(48, 16), dim3(32, 8)>>>(w_qkv);
    conv_x_f16<<<16384, 256>>>(x);
    conv_w_f16<<<3072, 256>>>();
    gemm_f16<0><<<dim3(12, 256), 256>>>(xf_p, wf_p, nullptr, nullptr);
    kv_reduce_mma<<<dim3(32, 16), 256>>>();
    kv_combine<<<dim3(32, 16), 256>>>();
    make_wbig<<<dim3(512, 4), 128>>>(w_out);
    z_split<<<32768, 128>>>();
    gemm_f16<1><<<dim3(4, 256), 256>>>(qzf_p, wbf_p, b_out, out);
}